// round 3
// baseline (speedup 1.0000x reference)
#include <cuda_runtime.h>

// Problem dims
#define Bb   64
#define Tt   256
#define Cc   384
#define Hh   6
#define HSZ  64
#define MM   (Bb*Tt)     // 16384 tokens
#define NQKV (3*Cc)      // 1152
#define FF   (4*Cc)      // 1536

// ---------------- scratch (device globals; no allocation) ----------------
__device__ float g_h   [MM*Cc];     // LN1 output
__device__ float g_qkv [MM*NQKV];   // fused q,k,v  [tok][ q(h,d) | k(h,d) | v(h,d) ]
__device__ float g_o   [MM*Cc];     // attention out (concat heads)
__device__ float g_x1  [MM*Cc];     // post-attention residual
__device__ float g_h2  [MM*Cc];     // LN2 output
__device__ float g_ffb [MM*FF];     // FF hidden
__device__ float g_wqkv[Cc*NQKV];   // packed QKV weight  [K=C][N=3C]

// ---------------- weight pack: (H,C,HS)x3 -> [C, 3C] ----------------
__global__ void pack_qkv_kernel(const float* __restrict__ Wq,
                                const float* __restrict__ Wk,
                                const float* __restrict__ Wv) {
    int idx = blockIdx.x * 256 + threadIdx.x;
    if (idx >= Cc * NQKV) return;
    int c   = idx / NQKV;
    int col = idx % NQKV;
    int which = col / Cc;
    int hd    = col % Cc;
    int h = hd / HSZ, d = hd % HSZ;
    const float* W = (which == 0) ? Wq : (which == 1) ? Wk : Wv;
    g_wqkv[idx] = W[(h * Cc + c) * HSZ + d];
}

// ---------------- LayerNorm: one block (128 thr) per row of 384 ----------------
__global__ void ln_kernel(const float* __restrict__ x,
                          const float* __restrict__ gamma,
                          const float* __restrict__ beta,
                          float* __restrict__ y) {
    int row = blockIdx.x;
    const float* xr = x + (long)row * Cc;
    float*       yr = y + (long)row * Cc;
    int tid = threadIdx.x;            // 128 threads, 3 elems each
    float v0 = xr[tid], v1 = xr[tid + 128], v2 = xr[tid + 256];
    float s  = v0 + v1 + v2;
    float sq = v0 * v0 + v1 * v1 + v2 * v2;
    #pragma unroll
    for (int o = 16; o > 0; o >>= 1) {
        s  += __shfl_down_sync(0xffffffffu, s,  o);
        sq += __shfl_down_sync(0xffffffffu, sq, o);
    }
    __shared__ float ss[4], sqs[4];
    int wid = tid >> 5, lid = tid & 31;
    if (lid == 0) { ss[wid] = s; sqs[wid] = sq; }
    __syncthreads();
    if (tid == 0) {
        float S  = ss[0] + ss[1] + ss[2] + ss[3];
        float SQ = sqs[0] + sqs[1] + sqs[2] + sqs[3];
        float mu  = S / (float)Cc;
        float var = SQ / (float)Cc - mu * mu;
        ss[0]  = mu;
        sqs[0] = rsqrtf(var + 1e-3f);
    }
    __syncthreads();
    float mu = ss[0], inv = sqs[0];
    yr[tid]       = (v0 - mu) * inv * gamma[tid]       + beta[tid];
    yr[tid + 128] = (v1 - mu) * inv * gamma[tid + 128] + beta[tid + 128];
    yr[tid + 256] = (v2 - mu) * inv * gamma[tid + 256] + beta[tid + 256];
}

// ---------------- fp32 SGEMM: C = A[M,K] * B[K,N] (+bias)(+res)(relu) ----------------
// 64x64 tile, BK=16, 256 threads, 4x4 per thread. All dims divide tiles.
template<bool BIAS, bool RES, bool RELU>
__global__ __launch_bounds__(256)
void gemm64_kernel(const float* __restrict__ A, const float* __restrict__ Bm,
                   const float* __restrict__ bias, const float* __restrict__ res,
                   float* __restrict__ Cm, int M, int N, int K) {
    __shared__ float As[16][68];   // [k][m], padded
    __shared__ float Bs[16][64];   // [k][n]
    int tid = threadIdx.x;
    int m0 = blockIdx.y * 64, n0 = blockIdx.x * 64;
    int ar = tid >> 2, ac = tid & 3;      // A: row ar, cols ac*4..
    int br = tid >> 4, bc = tid & 15;     // B: row br, cols bc*4..
    int trow = (tid >> 4) * 4, tcol = (tid & 15) * 4;
    float acc[4][4] = {};

    const float* Ap = A + (long)(m0 + ar) * K + ac * 4;
    const float* Bp = Bm + (long)br * N + n0 + bc * 4;

    for (int k0 = 0; k0 < K; k0 += 16) {
        float4 av = *(const float4*)(Ap + k0);
        As[ac * 4 + 0][ar] = av.x;
        As[ac * 4 + 1][ar] = av.y;
        As[ac * 4 + 2][ar] = av.z;
        As[ac * 4 + 3][ar] = av.w;
        float4 bv = *(const float4*)(Bp + (long)k0 * N);
        *(float4*)&Bs[br][bc * 4] = bv;
        __syncthreads();
        #pragma unroll
        for (int k = 0; k < 16; k++) {
            float4 a = *(float4*)&As[k][trow];
            float4 b = *(float4*)&Bs[k][tcol];
            acc[0][0] += a.x * b.x; acc[0][1] += a.x * b.y; acc[0][2] += a.x * b.z; acc[0][3] += a.x * b.w;
            acc[1][0] += a.y * b.x; acc[1][1] += a.y * b.y; acc[1][2] += a.y * b.z; acc[1][3] += a.y * b.w;
            acc[2][0] += a.z * b.x; acc[2][1] += a.z * b.y; acc[2][2] += a.z * b.z; acc[2][3] += a.z * b.w;
            acc[3][0] += a.w * b.x; acc[3][1] += a.w * b.y; acc[3][2] += a.w * b.z; acc[3][3] += a.w * b.w;
        }
        __syncthreads();
    }
    #pragma unroll
    for (int i = 0; i < 4; i++) {
        int row = m0 + trow + i;
        #pragma unroll
        for (int j = 0; j < 4; j++) {
            int col = n0 + tcol + j;
            float v = acc[i][j];
            if (BIAS) v += bias[col];
            if (RES)  v += res[(long)row * N + col];
            if (RELU) v = fmaxf(v, 0.f);
            Cm[(long)row * N + col] = v;
        }
    }
}

// ---------------- causal attention: 1 thread = 1 query row, online softmax ----------------
__global__ __launch_bounds__(64)
void attn_kernel(const float* __restrict__ qkv, float* __restrict__ o) {
    __shared__ float4 Kt[64][16];
    __shared__ float4 Vt[64][16];
    int b = blockIdx.z, h = blockIdx.y;
    int tq = blockIdx.x * 64 + threadIdx.x;

    const float* qrow = qkv + ((long)(b * Tt + tq)) * NQKV + h * HSZ;
    float4 q[16];
    #pragma unroll
    for (int i = 0; i < 16; i++) q[i] = *(const float4*)(qrow + 4 * i);

    float4 acc[16];
    #pragma unroll
    for (int i = 0; i < 16; i++) acc[i] = make_float4(0.f, 0.f, 0.f, 0.f);
    float m = -1e30f, l = 0.f;
    const float scale = 0.125f;  // HS^-0.5

    for (int kt = 0; kt <= blockIdx.x; kt++) {
        int s = kt * 64 + threadIdx.x;
        const float* kr = qkv + ((long)(b * Tt + s)) * NQKV + Cc + h * HSZ;
        const float* vr = kr + Cc;
        #pragma unroll
        for (int i = 0; i < 16; i++) {
            Kt[threadIdx.x][i] = *(const float4*)(kr + 4 * i);
            Vt[threadIdx.x][i] = *(const float4*)(vr + 4 * i);
        }
        __syncthreads();

        int jmax = min(64, tq - kt * 64 + 1);   // causal bound within tile
        for (int j = 0; j < jmax; j++) {
            float sd = 0.f;
            #pragma unroll
            for (int i = 0; i < 16; i++) {
                float4 kk = Kt[j][i];
                sd += q[i].x * kk.x + q[i].y * kk.y + q[i].z * kk.z + q[i].w * kk.w;
            }
            sd *= scale;
            float p;
            if (sd > m) {
                float corr = __expf(m - sd);
                l *= corr;
                #pragma unroll
                for (int i = 0; i < 16; i++) {
                    acc[i].x *= corr; acc[i].y *= corr; acc[i].z *= corr; acc[i].w *= corr;
                }
                m = sd;
                p = 1.f;
            } else {
                p = __expf(sd - m);
            }
            l += p;
            #pragma unroll
            for (int i = 0; i < 16; i++) {
                float4 vv = Vt[j][i];
                acc[i].x += p * vv.x; acc[i].y += p * vv.y;
                acc[i].z += p * vv.z; acc[i].w += p * vv.w;
            }
        }
        __syncthreads();
    }

    float inv = 1.f / l;
    float* orow = o + ((long)(b * Tt + tq)) * Cc + h * HSZ;
    #pragma unroll
    for (int i = 0; i < 16; i++) {
        float4 v = acc[i];
        v.x *= inv; v.y *= inv; v.z *= inv; v.w *= inv;
        *(float4*)(orow + 4 * i) = v;
    }
}

// ---------------- host launch ----------------
static float* sym_addr(const void* symbol) {
    void* p = nullptr;
    cudaGetSymbolAddress(&p, symbol);
    return (float*)p;
}

extern "C" void kernel_launch(void* const* d_in, const int* in_sizes, int n_in,
                              void* d_out, int out_size) {
    const float* x   = (const float*)d_in[0];
    const float* Wq  = (const float*)d_in[1];
    const float* Wk  = (const float*)d_in[2];
    const float* Wv  = (const float*)d_in[3];
    const float* Wp  = (const float*)d_in[4];
    const float* bp  = (const float*)d_in[5];
    const float* W1  = (const float*)d_in[6];
    const float* b1  = (const float*)d_in[7];
    const float* W2  = (const float*)d_in[8];
    const float* b2  = (const float*)d_in[9];
    const float* g1  = (const float*)d_in[10];
    const float* be1 = (const float*)d_in[11];
    const float* g2  = (const float*)d_in[12];
    const float* be2 = (const float*)d_in[13];
    float* out = (float*)d_out;

    float* p_h    = sym_addr(g_h);
    float* p_qkv  = sym_addr(g_qkv);
    float* p_o    = sym_addr(g_o);
    float* p_x1   = sym_addr(g_x1);
    float* p_h2   = sym_addr(g_h2);
    float* p_ff   = sym_addr(g_ffb);
    float* p_wqkv = sym_addr(g_wqkv);

    // 1. pack QKV weights into one GEMM B-matrix
    pack_qkv_kernel<<<(Cc * NQKV + 255) / 256, 256>>>(Wq, Wk, Wv);
    // 2. LN1
    ln_kernel<<<MM, 128>>>(x, g1, be1, p_h);
    // 3. fused QKV projection: [16384,384] x [384,1152]
    gemm64_kernel<false, false, false><<<dim3(NQKV / 64, MM / 64), 256>>>(
        p_h, p_wqkv, nullptr, nullptr, p_qkv, MM, NQKV, Cc);
    // 4. causal attention
    attn_kernel<<<dim3(Tt / 64, Hh, Bb), 64>>>(p_qkv, p_o);
    // 5. output projection + bias + residual
    gemm64_kernel<true, true, false><<<dim3(Cc / 64, MM / 64), 256>>>(
        p_o, Wp, bp, x, p_x1, MM, Cc, Cc);
    // 6. LN2
    ln_kernel<<<MM, 128>>>(p_x1, g2, be2, p_h2);
    // 7. FF1 + bias + relu: [16384,384] x [384,1536]
    gemm64_kernel<true, false, true><<<dim3(FF / 64, MM / 64), 256>>>(
        p_h2, W1, b1, nullptr, p_ff, MM, FF, Cc);
    // 8. FF2 + bias + residual -> final output
    gemm64_kernel<true, true, false><<<dim3(Cc / 64, MM / 64), 256>>>(
        p_ff, W2, b2, p_x1, out, MM, Cc, FF);
}

// round 6
// speedup vs baseline: 1.7768x; 1.7768x over previous
#include <cuda_runtime.h>
#include <cuda_bf16.h>
#include <cstdint>

// Problem dims
#define Bb   64
#define Tt   256
#define Cc   384
#define Hh   6
#define HSZ  64
#define MM   (Bb*Tt)     // 16384 tokens
#define NQKV (3*Cc)      // 1152
#define FF   (4*Cc)      // 1536

// ================= helpers =================
__device__ __forceinline__ uint32_t smem_u32(const void* p) {
    uint32_t a;
    asm("{ .reg .u64 t; cvta.to.shared.u64 t, %1; cvt.u32.u64 %0, t; }" : "=r"(a) : "l"(p));
    return a;
}
#define SMEM_SWIZZLE_128B(off) ((off) ^ (((off) >> 3) & 0x70))

#define CP_ASYNC16(dst, src) \
    asm volatile("cp.async.cg.shared.global [%0], [%1], 16;" :: "r"(dst), "l"(src))
#define CP_COMMIT() asm volatile("cp.async.commit_group;" ::: "memory")
#define CP_WAIT(n)  asm volatile("cp.async.wait_group %0;" :: "n"(n) : "memory")

#define LDSM_X4(r0, r1, r2, r3, addr) \
    asm volatile("ldmatrix.sync.aligned.m8n8.x4.shared.b16 {%0,%1,%2,%3}, [%4];" \
        : "=r"(r0), "=r"(r1), "=r"(r2), "=r"(r3) : "r"(addr))

#define MMA16816(d, a, b) \
    asm volatile("mma.sync.aligned.m16n8k16.row.col.f32.bf16.bf16.f32 " \
        "{%0,%1,%2,%3}, {%4,%5,%6,%7}, {%8,%9}, {%0,%1,%2,%3};" \
        : "+f"((d)[0]), "+f"((d)[1]), "+f"((d)[2]), "+f"((d)[3]) \
        : "r"((a)[0]), "r"((a)[1]), "r"((a)[2]), "r"((a)[3]), "r"((b)[0]), "r"((b)[1]))

// ================= scratch (device globals) =================
__device__ __align__(16) __nv_bfloat16 g_h_hi [MM*Cc];
__device__ __align__(16) __nv_bfloat16 g_h_lo [MM*Cc];
__device__ __align__(16) float         g_qkv  [MM*NQKV];
__device__ __align__(16) __nv_bfloat16 g_o_hi [MM*Cc];
__device__ __align__(16) __nv_bfloat16 g_o_lo [MM*Cc];
__device__ __align__(16) float         g_x1   [MM*Cc];
__device__ __align__(16) __nv_bfloat16 g_h2_hi[MM*Cc];
__device__ __align__(16) __nv_bfloat16 g_h2_lo[MM*Cc];
__device__ __align__(16) __nv_bfloat16 g_ff_hi[MM*FF];
__device__ __align__(16) __nv_bfloat16 g_ff_lo[MM*FF];
// packed/transposed weights [N][K] bf16 hi/lo
__device__ __align__(16) __nv_bfloat16 g_wqkvT_hi[NQKV*Cc];
__device__ __align__(16) __nv_bfloat16 g_wqkvT_lo[NQKV*Cc];
__device__ __align__(16) __nv_bfloat16 g_wpT_hi[Cc*Cc];
__device__ __align__(16) __nv_bfloat16 g_wpT_lo[Cc*Cc];
__device__ __align__(16) __nv_bfloat16 g_w1T_hi[FF*Cc];
__device__ __align__(16) __nv_bfloat16 g_w1T_lo[FF*Cc];
__device__ __align__(16) __nv_bfloat16 g_w2T_hi[Cc*FF];
__device__ __align__(16) __nv_bfloat16 g_w2T_lo[Cc*FF];

__device__ __forceinline__ void split2(float x, __nv_bfloat16& hi, __nv_bfloat16& lo) {
    hi = __float2bfloat16(x);
    lo = __float2bfloat16(x - __bfloat162float(hi));
}

// ================= weight pack kernels =================
__global__ void pack_qkvT_kernel(const float* __restrict__ Wq,
                                 const float* __restrict__ Wk,
                                 const float* __restrict__ Wv) {
    int idx = blockIdx.x * 256 + threadIdx.x;
    if (idx >= NQKV * Cc) return;
    int n = idx / Cc, k = idx % Cc;
    int which = n / Cc;
    int hd    = n % Cc;
    int h = hd / HSZ, d = hd % HSZ;
    const float* W = (which == 0) ? Wq : (which == 1) ? Wk : Wv;
    split2(W[(h * Cc + k) * HSZ + d], g_wqkvT_hi[idx], g_wqkvT_lo[idx]);
}

// generic transpose+split: out[n][k] = W[k*N + n]   (W is [K][N])
__global__ void convT_kernel(const float* __restrict__ W,
                             __nv_bfloat16* __restrict__ hi,
                             __nv_bfloat16* __restrict__ lo, int K, int N) {
    int idx = blockIdx.x * 256 + threadIdx.x;
    if (idx >= N * K) return;
    int n = idx / K, k = idx % K;
    split2(W[(size_t)k * N + n], hi[idx], lo[idx]);
}

// ================= LayerNorm -> bf16 hi/lo =================
__global__ void ln_kernel(const float* __restrict__ x,
                          const float* __restrict__ gamma,
                          const float* __restrict__ beta,
                          __nv_bfloat16* __restrict__ yhi,
                          __nv_bfloat16* __restrict__ ylo) {
    int row = blockIdx.x;
    const float* xr = x + (size_t)row * Cc;
    int tid = threadIdx.x;  // 128 threads, 3 elems each
    float v0 = xr[tid], v1 = xr[tid + 128], v2 = xr[tid + 256];
    float s  = v0 + v1 + v2;
    float sq = v0 * v0 + v1 * v1 + v2 * v2;
    #pragma unroll
    for (int o = 16; o > 0; o >>= 1) {
        s  += __shfl_down_sync(0xffffffffu, s,  o);
        sq += __shfl_down_sync(0xffffffffu, sq, o);
    }
    __shared__ float ss[4], sqs[4];
    int wid = tid >> 5, lid = tid & 31;
    if (lid == 0) { ss[wid] = s; sqs[wid] = sq; }
    __syncthreads();
    if (tid == 0) {
        float S  = ss[0] + ss[1] + ss[2] + ss[3];
        float SQ = sqs[0] + sqs[1] + sqs[2] + sqs[3];
        float mu  = S / (float)Cc;
        float var = SQ / (float)Cc - mu * mu;
        ss[0]  = mu;
        sqs[0] = rsqrtf(var + 1e-3f);
    }
    __syncthreads();
    float mu = ss[0], inv = sqs[0];
    size_t base = (size_t)row * Cc;
    float y0 = (v0 - mu) * inv * gamma[tid]       + beta[tid];
    float y1 = (v1 - mu) * inv * gamma[tid + 128] + beta[tid + 128];
    float y2 = (v2 - mu) * inv * gamma[tid + 256] + beta[tid + 256];
    split2(y0, yhi[base + tid],       ylo[base + tid]);
    split2(y1, yhi[base + tid + 128], ylo[base + tid + 128]);
    split2(y2, yhi[base + tid + 256], ylo[base + tid + 256]);
}

// ================= mma.sync split-bf16 GEMM =================
// C[M,N] = A[M,K] * B^T  with A=[M][K] hi/lo bf16, B=[N][K] hi/lo bf16.
// CTA tile 128x128, BK=64, cp.async double buffer, 8 warps each 64x32.
// SMEM per buffer: Ahi 16K | Alo 16K | Bhi 16K | Blo 16K = 64KB. Two buffers.
#define GEMM_DSMEM (1024 + 2 * 65536)

__device__ __forceinline__ void load_tile_async(const __nv_bfloat16* __restrict__ src,
                                                int row0, int k0, int Ktot,
                                                uint32_t dstbase, int tid) {
    #pragma unroll
    for (int j = 0; j < 4; j++) {
        int idx = tid + j * 256;         // 1024 x 16B = 128 rows x 128B
        int r = idx >> 3, c16 = idx & 7;
        const __nv_bfloat16* g = src + (size_t)(row0 + r) * Ktot + k0 + c16 * 8;
        uint32_t s = dstbase + SMEM_SWIZZLE_128B((uint32_t)(r * 128 + c16 * 16));
        CP_ASYNC16(s, g);
    }
}

template<int BIAS, int RES, int RELU, int F32OUT, int BFOUT>
__global__ __launch_bounds__(256)
void mma_gemm_kernel(const __nv_bfloat16* __restrict__ Ahi, const __nv_bfloat16* __restrict__ Alo,
                     const __nv_bfloat16* __restrict__ Bhi, const __nv_bfloat16* __restrict__ Blo,
                     const float* __restrict__ bias, const float* __restrict__ res,
                     float* __restrict__ Cf,
                     __nv_bfloat16* __restrict__ Chi, __nv_bfloat16* __restrict__ Clo,
                     int M, int N, int K) {
    extern __shared__ char dsm[];
    uint32_t raw  = smem_u32(dsm);
    uint32_t base = (raw + 1023) & ~1023u;

    int tid = threadIdx.x, wid = tid >> 5, lane = tid & 31;
    int warp_m = (wid >> 2) * 64;   // 0 or 64
    int warp_n = (wid & 3) * 32;    // 0,32,64,96
    int m0 = blockIdx.y * 128, n0 = blockIdx.x * 128;
    int nch = K >> 6;

    float acc[4][4][4];
    #pragma unroll
    for (int a = 0; a < 4; a++)
        #pragma unroll
        for (int b = 0; b < 4; b++)
            #pragma unroll
            for (int c = 0; c < 4; c++) acc[a][b][c] = 0.f;

    // prologue: chunk 0 -> buffer 0
    load_tile_async(Ahi, m0, 0, K, base + 0,     tid);
    load_tile_async(Alo, m0, 0, K, base + 16384, tid);
    load_tile_async(Bhi, n0, 0, K, base + 32768, tid);
    load_tile_async(Blo, n0, 0, K, base + 49152, tid);
    CP_COMMIT();

    // ldmatrix lane mapping
    int q = lane >> 3, rin = lane & 7;
    int a_row_off = (q & 1) * 8 + rin;       // + mf*16
    int a_col_off = (q >> 1) * 8;            // + ks*16
    int b_row_off = (q >> 1) * 8 + rin;      // + nf2*16
    int b_col_off = (q & 1) * 8;             // + ks*16

    for (int i = 0; i < nch; i++) {
        if (i + 1 < nch) {
            uint32_t nb = base + ((i + 1) & 1) * 65536;
            int k0 = (i + 1) << 6;
            load_tile_async(Ahi, m0, k0, K, nb + 0,     tid);
            load_tile_async(Alo, m0, k0, K, nb + 16384, tid);
            load_tile_async(Bhi, n0, k0, K, nb + 32768, tid);
            load_tile_async(Blo, n0, k0, K, nb + 49152, tid);
            CP_COMMIT();
            CP_WAIT(1);
        } else {
            CP_WAIT(0);
        }
        __syncthreads();

        uint32_t buf = base + (i & 1) * 65536;
        uint32_t sAhi = buf + 0, sAlo = buf + 16384;
        uint32_t sBhi = buf + 32768, sBlo = buf + 49152;

        #pragma unroll
        for (int ks = 0; ks < 4; ks++) {
            uint32_t ahi[4][4], alo[4][4], bhi[4][2], blo[4][2];
            #pragma unroll
            for (int mf = 0; mf < 4; mf++) {
                uint32_t off = (uint32_t)((warp_m + mf * 16 + a_row_off) * 128 +
                                          (ks * 16 + a_col_off) * 2);
                LDSM_X4(ahi[mf][0], ahi[mf][1], ahi[mf][2], ahi[mf][3],
                        sAhi + SMEM_SWIZZLE_128B(off));
                LDSM_X4(alo[mf][0], alo[mf][1], alo[mf][2], alo[mf][3],
                        sAlo + SMEM_SWIZZLE_128B(off));
            }
            #pragma unroll
            for (int nf2 = 0; nf2 < 2; nf2++) {
                uint32_t off = (uint32_t)((warp_n + nf2 * 16 + b_row_off) * 128 +
                                          (ks * 16 + b_col_off) * 2);
                LDSM_X4(bhi[nf2 * 2][0], bhi[nf2 * 2][1], bhi[nf2 * 2 + 1][0], bhi[nf2 * 2 + 1][1],
                        sBhi + SMEM_SWIZZLE_128B(off));
                LDSM_X4(blo[nf2 * 2][0], blo[nf2 * 2][1], blo[nf2 * 2 + 1][0], blo[nf2 * 2 + 1][1],
                        sBlo + SMEM_SWIZZLE_128B(off));
            }
            #pragma unroll
            for (int mf = 0; mf < 4; mf++)
                #pragma unroll
                for (int nf = 0; nf < 4; nf++) MMA16816(acc[mf][nf], ahi[mf], bhi[nf]);
            #pragma unroll
            for (int mf = 0; mf < 4; mf++)
                #pragma unroll
                for (int nf = 0; nf < 4; nf++) MMA16816(acc[mf][nf], alo[mf], bhi[nf]);
            #pragma unroll
            for (int mf = 0; mf < 4; mf++)
                #pragma unroll
                for (int nf = 0; nf < 4; nf++) MMA16816(acc[mf][nf], ahi[mf], blo[nf]);
        }
        __syncthreads();
    }

    // epilogue: direct register -> global with fused ops
    int tr = lane >> 2, tc = (lane & 3) * 2;
    #pragma unroll
    for (int mf = 0; mf < 4; mf++) {
        #pragma unroll
        for (int nf = 0; nf < 4; nf++) {
            int col = n0 + warp_n + nf * 8 + tc;
            #pragma unroll
            for (int half = 0; half < 2; half++) {
                int row = m0 + warp_m + mf * 16 + tr + half * 8;
                float v0 = acc[mf][nf][half * 2 + 0];
                float v1 = acc[mf][nf][half * 2 + 1];
                if (BIAS) { v0 += bias[col]; v1 += bias[col + 1]; }
                size_t oidx = (size_t)row * N + col;
                if (RES)  { v0 += res[oidx]; v1 += res[oidx + 1]; }
                if (RELU) { v0 = fmaxf(v0, 0.f); v1 = fmaxf(v1, 0.f); }
                if (F32OUT) {
                    Cf[oidx] = v0; Cf[oidx + 1] = v1;
                }
                if (BFOUT) {
                    split2(v0, Chi[oidx], Clo[oidx]);
                    split2(v1, Chi[oidx + 1], Clo[oidx + 1]);
                }
            }
        }
    }
}

// ================= causal attention (fp32) =================
__global__ __launch_bounds__(64)
void attn_kernel(const float* __restrict__ qkv,
                 __nv_bfloat16* __restrict__ ohi, __nv_bfloat16* __restrict__ olo) {
    __shared__ float4 Kt[64][16];
    __shared__ float4 Vt[64][16];
    int b = blockIdx.z, h = blockIdx.y;
    int tq = blockIdx.x * 64 + threadIdx.x;

    const float* qrow = qkv + ((size_t)(b * Tt + tq)) * NQKV + h * HSZ;
    float4 q[16];
    #pragma unroll
    for (int i = 0; i < 16; i++) q[i] = *(const float4*)(qrow + 4 * i);

    float4 acc[16];
    #pragma unroll
    for (int i = 0; i < 16; i++) acc[i] = make_float4(0.f, 0.f, 0.f, 0.f);
    float m = -1e30f, l = 0.f;
    const float scale = 0.125f;

    for (int kt = 0; kt <= blockIdx.x; kt++) {
        int s = kt * 64 + threadIdx.x;
        const float* kr = qkv + ((size_t)(b * Tt + s)) * NQKV + Cc + h * HSZ;
        const float* vr = kr + Cc;
        #pragma unroll
        for (int i = 0; i < 16; i++) {
            Kt[threadIdx.x][i] = *(const float4*)(kr + 4 * i);
            Vt[threadIdx.x][i] = *(const float4*)(vr + 4 * i);
        }
        __syncthreads();

        int jmax = min(64, tq - kt * 64 + 1);
        for (int j = 0; j < jmax; j++) {
            float sd = 0.f;
            #pragma unroll
            for (int i = 0; i < 16; i++) {
                float4 kk = Kt[j][i];
                sd += q[i].x * kk.x + q[i].y * kk.y + q[i].z * kk.z + q[i].w * kk.w;
            }
            sd *= scale;
            float p;
            if (sd > m) {
                float corr = __expf(m - sd);
                l *= corr;
                #pragma unroll
                for (int i = 0; i < 16; i++) {
                    acc[i].x *= corr; acc[i].y *= corr; acc[i].z *= corr; acc[i].w *= corr;
                }
                m = sd;
                p = 1.f;
            } else {
                p = __expf(sd - m);
            }
            l += p;
            #pragma unroll
            for (int i = 0; i < 16; i++) {
                float4 vv = Vt[j][i];
                acc[i].x += p * vv.x; acc[i].y += p * vv.y;
                acc[i].z += p * vv.z; acc[i].w += p * vv.w;
            }
        }
        __syncthreads();
    }

    float inv = 1.f / l;
    size_t obase = ((size_t)(b * Tt + tq)) * Cc + h * HSZ;
    #pragma unroll
    for (int i = 0; i < 16; i++) {
        float4 v = acc[i];
        split2(v.x * inv, ohi[obase + 4 * i + 0], olo[obase + 4 * i + 0]);
        split2(v.y * inv, ohi[obase + 4 * i + 1], olo[obase + 4 * i + 1]);
        split2(v.z * inv, ohi[obase + 4 * i + 2], olo[obase + 4 * i + 2]);
        split2(v.w * inv, ohi[obase + 4 * i + 3], olo[obase + 4 * i + 3]);
    }
}

// ================= host launch =================
template <typename T>
static T* sym_addr(const T* symbol) {
    void* p = nullptr;
    cudaGetSymbolAddress(&p, (const void*)symbol);
    return (T*)p;
}

extern "C" void kernel_launch(void* const* d_in, const int* in_sizes, int n_in,
                              void* d_out, int out_size) {
    const float* x   = (const float*)d_in[0];
    const float* Wq  = (const float*)d_in[1];
    const float* Wk  = (const float*)d_in[2];
    const float* Wv  = (const float*)d_in[3];
    const float* Wp  = (const float*)d_in[4];
    const float* bp  = (const float*)d_in[5];
    const float* W1  = (const float*)d_in[6];
    const float* b1  = (const float*)d_in[7];
    const float* W2  = (const float*)d_in[8];
    const float* b2  = (const float*)d_in[9];
    const float* g1  = (const float*)d_in[10];
    const float* be1 = (const float*)d_in[11];
    const float* g2  = (const float*)d_in[12];
    const float* be2 = (const float*)d_in[13];
    float* out = (float*)d_out;

    __nv_bfloat16* p_h_hi  = sym_addr(g_h_hi);
    __nv_bfloat16* p_h_lo  = sym_addr(g_h_lo);
    float*         p_qkv   = sym_addr(g_qkv);
    __nv_bfloat16* p_o_hi  = sym_addr(g_o_hi);
    __nv_bfloat16* p_o_lo  = sym_addr(g_o_lo);
    float*         p_x1    = sym_addr(g_x1);
    __nv_bfloat16* p_h2_hi = sym_addr(g_h2_hi);
    __nv_bfloat16* p_h2_lo = sym_addr(g_h2_lo);
    __nv_bfloat16* p_ff_hi = sym_addr(g_ff_hi);
    __nv_bfloat16* p_ff_lo = sym_addr(g_ff_lo);
    __nv_bfloat16* p_wqkvT_hi = sym_addr(g_wqkvT_hi);
    __nv_bfloat16* p_wqkvT_lo = sym_addr(g_wqkvT_lo);
    __nv_bfloat16* p_wpT_hi   = sym_addr(g_wpT_hi);
    __nv_bfloat16* p_wpT_lo   = sym_addr(g_wpT_lo);
    __nv_bfloat16* p_w1T_hi   = sym_addr(g_w1T_hi);
    __nv_bfloat16* p_w1T_lo   = sym_addr(g_w1T_lo);
    __nv_bfloat16* p_w2T_hi   = sym_addr(g_w2T_hi);
    __nv_bfloat16* p_w2T_lo   = sym_addr(g_w2T_lo);

    cudaFuncSetAttribute(mma_gemm_kernel<0,0,0,1,0>, cudaFuncAttributeMaxDynamicSharedMemorySize, GEMM_DSMEM);
    cudaFuncSetAttribute(mma_gemm_kernel<1,1,0,1,0>, cudaFuncAttributeMaxDynamicSharedMemorySize, GEMM_DSMEM);
    cudaFuncSetAttribute(mma_gemm_kernel<1,0,1,0,1>, cudaFuncAttributeMaxDynamicSharedMemorySize, GEMM_DSMEM);

    // 1. weight packing (transposed + bf16 split)
    pack_qkvT_kernel<<<(NQKV * Cc + 255) / 256, 256>>>(Wq, Wk, Wv);
    convT_kernel<<<(Cc * Cc + 255) / 256, 256>>>(Wp, p_wpT_hi, p_wpT_lo, Cc, Cc);
    convT_kernel<<<(Cc * FF + 255) / 256, 256>>>(W1, p_w1T_hi, p_w1T_lo, Cc, FF);
    convT_kernel<<<(FF * Cc + 255) / 256, 256>>>(W2, p_w2T_hi, p_w2T_lo, FF, Cc);

    // 2. LN1 -> bf16 split
    ln_kernel<<<MM, 128>>>(x, g1, be1, p_h_hi, p_h_lo);

    // 3. fused QKV projection: [16384,384] x [384,1152] -> fp32 qkv
    mma_gemm_kernel<0,0,0,1,0><<<dim3(NQKV / 128, MM / 128), 256, GEMM_DSMEM>>>(
        p_h_hi, p_h_lo, p_wqkvT_hi, p_wqkvT_lo,
        nullptr, nullptr, p_qkv, nullptr, nullptr, MM, NQKV, Cc);

    // 4. causal attention -> o bf16 split
    attn_kernel<<<dim3(Tt / 64, Hh, Bb), 64>>>(p_qkv, p_o_hi, p_o_lo);

    // 5. output projection + bias + residual -> x1 fp32
    mma_gemm_kernel<1,1,0,1,0><<<dim3(Cc / 128, MM / 128), 256, GEMM_DSMEM>>>(
        p_o_hi, p_o_lo, p_wpT_hi, p_wpT_lo,
        bp, x, p_x1, nullptr, nullptr, MM, Cc, Cc);

    // 6. LN2 -> bf16 split
    ln_kernel<<<MM, 128>>>(p_x1, g2, be2, p_h2_hi, p_h2_lo);

    // 7. FF1 + bias + relu -> ff bf16 split
    mma_gemm_kernel<1,0,1,0,1><<<dim3(FF / 128, MM / 128), 256, GEMM_DSMEM>>>(
        p_h2_hi, p_h2_lo, p_w1T_hi, p_w1T_lo,
        b1, nullptr, nullptr, p_ff_hi, p_ff_lo, MM, FF, Cc);

    // 8. FF2 + bias + residual -> final output fp32
    mma_gemm_kernel<1,1,0,1,0><<<dim3(Cc / 128, MM / 128), 256, GEMM_DSMEM>>>(
        p_ff_hi, p_ff_lo, p_w2T_hi, p_w2T_lo,
        b2, p_x1, out, nullptr, nullptr, MM, Cc, FF);
}